// round 15
// baseline (speedup 1.0000x reference)
#include <cuda_runtime.h>
#include <math.h>

// Problem dims (fixed by the reference)
namespace cfg {
constexpr int V = 32000, E = 512, H = 1024, S = 50, B = 64, T = 10;
constexpr int H2 = 2 * H, H3 = 3 * H;
constexpr int KSPLIT = 8;   // K slices for the GRU (KLEN = 128)
}
using namespace cfg;

// ---------------- device scratch (no allocations allowed) ----------------
__device__ float g_gi[T * B * H3];             // emb[dec_in] @ w_ih^T + b_ih
__device__ float g_ghp[2 * KSPLIT * B * H3];   // split-K partials, parity double-buffered
__device__ float g_hs[T * B * H];              // GRU hidden states [T, B, H]
__device__ float g_uk[B * S * H];              // enc @ ua_w^T + ua_b, rows (s*B+b)
__device__ float g_wq[T * B * H];              // hs @ wa_w^T + wa_b [T*B, H]
__device__ float g_sc[T * B * S];              // raw scores [T*B, S]
// g_cnt[t]              : global barrier1 (partials visible), t = 0..T-1
// g_cnt[T + t*KSPLIT+z] : z-group barrier2 (h z-slice visible)
__device__ int   g_cnt[T + T * KSPLIT];

// ---------------- small intrinsics ----------------
__device__ __forceinline__ float tanha(float x) {
    float y;
    asm("tanh.approx.f32 %0, %1;" : "=f"(y) : "f"(x));
    return y;
}
__device__ __forceinline__ void mma8(float* c, const unsigned* a, const unsigned* b) {
    asm volatile(
        "mma.sync.aligned.m16n8k8.row.col.f32.tf32.tf32.f32 "
        "{%0,%1,%2,%3}, {%4,%5,%6,%7}, {%8,%9}, {%0,%1,%2,%3};"
        : "+f"(c[0]), "+f"(c[1]), "+f"(c[2]), "+f"(c[3])
        : "r"(a[0]), "r"(a[1]), "r"(a[2]), "r"(a[3]), "r"(b[0]), "r"(b[1]));
}
__device__ __forceinline__ void cp16(float* smem_dst, const float* gptr) {
    unsigned s = (unsigned)__cvta_generic_to_shared(smem_dst);
    asm volatile("cp.async.cg.shared.global [%0], [%1], 16;\n" :: "r"(s), "l"(gptr));
}
// ldmatrix on 32-bit data: m8n8.b16 over 8x(16B rows) => 8x4 b32 matrix;
// thread t receives b32 element (row t/4, col t%4) == tf32 frag layout.
__device__ __forceinline__ void ldsm_x4(unsigned* r, unsigned addr) {
    asm volatile("ldmatrix.sync.aligned.m8n8.x4.shared.b16 {%0,%1,%2,%3}, [%4];"
                 : "=r"(r[0]), "=r"(r[1]), "=r"(r[2]), "=r"(r[3]) : "r"(addr));
}
__device__ __forceinline__ void ldsm_x2(unsigned* r, unsigned addr) {
    asm volatile("ldmatrix.sync.aligned.m8n8.x2.shared.b16 {%0,%1}, [%2];"
                 : "=r"(r[0]), "=r"(r[1]) : "r"(addr));
}
// RNA rounding for tf32 applied on the fragment register (same numerics as
// cvt.rna: +half-ulp of the 10-bit mantissa before the mma truncates).
#define RNA4(f) { f[0] += 0x1000u; f[1] += 0x1000u; f[2] += 0x1000u; f[3] += 0x1000u; }
#define RNA2(f) { f[0] += 0x1000u; f[1] += 0x1000u; }

// ============ unified 128x128 tf32 GEMM body (proven round-10 loop) =========
__device__ __forceinline__ void gemm128_body(
    const float* __restrict__ A, const float* __restrict__ W,
    const float* __restrict__ bias, float* __restrict__ C,
    int N, int K, int bm, int bn, bool gather, const int* __restrict__ target,
    float* sm) {
    constexpr int BM = 128, BN = 128, WM = 4, WN = 2;
    constexpr int BK = 32, NT = 256;
    constexpr int TM = BM / WM, TN = BN / WN;   // 32, 64
    constexpr int MM = TM / 16, MN = TN / 8;    // 2, 8
    constexpr int LDSR = BK + 4;                // 36 floats = 144 B rows
    constexpr int A_LD = 4, B_LD = 4;

    float* Asm = sm;                      // [2][BM*LDSR]
    float* Bsm = sm + 2 * BM * LDSR;      // [2][BN*LDSR]

    const int tid = threadIdx.x;
    const int warp = tid >> 5, lane = tid & 31;
    const int wm = warp / WN, wn = warp % WN;
    const int g = lane >> 2, tg = lane & 3;

    const float* abase[A_LD];
    const float* bbase[B_LD];
    int aoff[A_LD], boff[B_LD];
#pragma unroll
    for (int i = 0; i < A_LD; i++) {
        int idx = tid + i * NT;
        int r = idx >> 3, kq = idx & 7;
        int m = bm + r;
        const float* ar;
        if (gather) {
            int t = m / B, b = m % B;
            int tok = (t == 0) ? 0 : target[b * T + (t - 1)];
            ar = A + (size_t)tok * K;
        } else {
            ar = A + (size_t)m * K;
        }
        abase[i] = ar + kq * 4;
        aoff[i] = r * LDSR + kq * 4;
    }
#pragma unroll
    for (int i = 0; i < B_LD; i++) {
        int idx = tid + i * NT;
        int r = idx >> 3, kq = idx & 7;
        bbase[i] = W + (size_t)(bn + r) * K + kq * 4;
        boff[i] = r * LDSR + kq * 4;
    }

    const int sub = lane >> 3, rw = lane & 7;
    const unsigned aB = (unsigned)__cvta_generic_to_shared(Asm) +
        ((unsigned)((wm * TM + rw + 8 * (sub & 1)) * LDSR + 4 * (sub >> 1))) * 4u;
    const unsigned bB = (unsigned)__cvta_generic_to_shared(Bsm) +
        ((unsigned)((wn * TN + rw) * LDSR + 4 * (sub & 1))) * 4u;

    float acc[MM][MN][4];
#pragma unroll
    for (int im = 0; im < MM; im++)
#pragma unroll
        for (int in = 0; in < MN; in++)
#pragma unroll
            for (int q = 0; q < 4; q++) acc[im][in][q] = 0.f;

    auto issue = [&](int k0, int buf) {
        float* as = Asm + buf * BM * LDSR;
        float* bs = Bsm + buf * BN * LDSR;
#pragma unroll
        for (int i = 0; i < A_LD; i++) cp16(as + aoff[i], abase[i] + k0);
#pragma unroll
        for (int i = 0; i < B_LD; i++) cp16(bs + boff[i], bbase[i] + k0);
        asm volatile("cp.async.commit_group;\n" ::);
    };

    issue(0, 0);
    const int KT = K / BK;
    for (int kt = 0; kt < KT; kt++) {
        if (kt + 1 < KT) {
            issue((kt + 1) * BK, (kt + 1) & 1);
            asm volatile("cp.async.wait_group 1;\n" ::);
        } else {
            asm volatile("cp.async.wait_group 0;\n" ::);
        }
        __syncthreads();

        const unsigned aBuf = aB + (unsigned)((kt & 1) * BM * LDSR) * 4u;
        const unsigned bBuf = bB + (unsigned)((kt & 1) * BN * LDSR) * 4u;
#pragma unroll
        for (int ks = 0; ks < 4; ks++) {
            const int kk = ks * 8;
            unsigned af[MM][4], bf[MN][2];
#pragma unroll
            for (int im = 0; im < MM; im++) {
                ldsm_x4(af[im], aBuf + (unsigned)(im * 16 * LDSR + kk) * 4u);
                RNA4(af[im]);
            }
#pragma unroll
            for (int in = 0; in < MN; in++) {
                ldsm_x2(bf[in], bBuf + (unsigned)(in * 8 * LDSR + kk) * 4u);
                RNA2(bf[in]);
            }
#pragma unroll
            for (int im = 0; im < MM; im++)
#pragma unroll
                for (int in = 0; in < MN; in++)
                    mma8(acc[im][in], af[im], bf[in]);
        }
        __syncthreads();
    }

#pragma unroll
    for (int im = 0; im < MM; im++) {
        int row0 = bm + wm * TM + im * 16 + g;
#pragma unroll
        for (int in = 0; in < MN; in++) {
            int col = bn + wn * TN + in * 8 + 2 * tg;
            float2 bb = *(const float2*)(bias + col);
            float* c = acc[im][in];
            *(float2*)(C + (size_t)row0 * N + col) = make_float2(c[0] + bb.x, c[1] + bb.y);
            *(float2*)(C + (size_t)(row0 + 8) * N + col) = make_float2(c[2] + bb.x, c[3] + bb.y);
        }
    }
}

// ---- dual GEMM: blocks 0..199 compute uk, 200..319 compute gi (one launch) --
// Also resets the GRU barrier counters (block 0) — runs before k_gru_all.
__global__ void __launch_bounds__(256, 2)
k_gemm_dual(const float* __restrict__ enc, const float* __restrict__ ua_w,
            const float* __restrict__ ua_b, float* __restrict__ uk,
            const float* __restrict__ emb, const float* __restrict__ w_ih,
            const float* __restrict__ b_ih, float* __restrict__ gi,
            const int* __restrict__ target) {
    extern __shared__ float sm[];
    const int bid = blockIdx.x;
    if (bid == 0 && threadIdx.x < T + T * KSPLIT) g_cnt[threadIdx.x] = 0;

    if (bid < 200) {
        // uk tile: M=3200 (25), N=1024 (8), K=2048
        int bx = bid & 7, by = bid >> 3;
        gemm128_body(enc, ua_w, ua_b, uk, H, H2, by * 128, bx * 128,
                     false, nullptr, sm);
    } else {
        // gi tile: M=640 (5), N=3072 (24), K=512, gathered A
        int idx = bid - 200;
        int bx = idx % 24, by = idx / 24;
        gemm128_body(emb, w_ih, b_ih, gi, H3, E, by * 128, bx * 128,
                     true, target, sm);
    }
}

// ---- wq GEMM (stand-alone, same proven body) --------------------------------
__global__ void __launch_bounds__(256, 2)
k_gemm_wq(const float* __restrict__ A, const float* __restrict__ W,
          const float* __restrict__ bias, float* __restrict__ C) {
    extern __shared__ float sm[];
    gemm128_body(A, W, bias, C, H, H, blockIdx.y * 128, blockIdx.x * 128,
                 false, nullptr, sm);
}

// ---------------- persistent GRU, weight-resident in smem -------------------
// Grid (16,1,8) = 128 blocks, 1 block/SM (smem) -> co-resident.
// Gate is z-sliced: block (bx,z) computes h columns [z*128, z*128+128) for
// b in [bx*4, bx*4+4) — exactly the columns it reads next step, so the
// h-visibility barrier is per-z-group (16 blocks). Partials are parity
// double-buffered to remove the WAR across steps.
__global__ void __launch_bounds__(256)
k_gru_all(const float* __restrict__ hidden, const float* __restrict__ whh,
          const float* __restrict__ gi_all, const float* __restrict__ b_hh_,
          float* __restrict__ part, float* __restrict__ hs) {
    constexpr int BM = 64, BN = 192, WM = 2, WN = 4;
    constexpr int NT = 256;
    constexpr int TM = BM / WM, TN = BN / WN;   // 32, 48
    constexpr int MM = TM / 16, MN = TN / 8;    // 2, 6
    constexpr int KLEN = H / KSPLIT;            // 128
    constexpr int LDSR = KLEN + 4;              // 132 floats = 528 B rows
    constexpr int NBLK = (H3 / BN) * KSPLIT;    // 128
    constexpr int ZBLK = H3 / BN;               // 16 blocks per z-group
    constexpr int A_CP = BM * (KLEN / 4) / NT;  // 8
    constexpr int B_CP = BN * (KLEN / 4) / NT;  // 24

    extern __shared__ float sm[];
    float* Bs = sm;                 // [BN][LDSR]  weights, resident
    float* As = sm + BN * LDSR;     // [BM][LDSR]  hprev slice, per step

    const int tid = threadIdx.x;
    const int warp = tid >> 5, lane = tid & 31;
    const int wm = warp / WN, wn = warp % WN;
    const int g = lane >> 2, tg = lane & 3;
    const int bx = blockIdx.x;            // 0..15
    const int bn = bx * BN;
    const int z = blockIdx.z;             // 0..7
    const int kstart = z * KLEN;

    // ---- load W_hh tile once (192 x 128 floats) ----
#pragma unroll
    for (int i = 0; i < B_CP; i++) {
        int idx = tid + i * NT;
        int r = idx >> 5, kq = idx & 31;
        cp16(Bs + r * LDSR + kq * 4, whh + (size_t)(bn + r) * H + kstart + kq * 4);
    }
    asm volatile("cp.async.commit_group;\n" ::);

    // ldmatrix lane-address bases
    const int sub = lane >> 3, rw = lane & 7;
    const unsigned aB = (unsigned)__cvta_generic_to_shared(As) +
        ((unsigned)((wm * TM + rw + 8 * (sub & 1)) * LDSR + 4 * (sub >> 1))) * 4u;
    const unsigned bB = (unsigned)__cvta_generic_to_shared(Bs) +
        ((unsigned)((wn * TN + rw) * LDSR + 4 * (sub & 1))) * 4u;

    for (int t = 0; t < T; t++) {
        const float* hprev = (t == 0) ? hidden : hs + (size_t)(t - 1) * B * H;
        const float* gi = gi_all + (size_t)t * B * H3;
        float* pbuf = part + (size_t)(t & 1) * KSPLIT * B * H3;
        float* C = pbuf + (size_t)z * B * H3;

        // ---- load hprev slice (64 x 128 floats) ----
#pragma unroll
        for (int i = 0; i < A_CP; i++) {
            int idx = tid + i * NT;
            int r = idx >> 5, kq = idx & 31;
            cp16(As + r * LDSR + kq * 4, hprev + (size_t)r * H + kstart + kq * 4);
        }
        asm volatile("cp.async.commit_group;\n" ::);
        asm volatile("cp.async.wait_group 0;\n" ::);
        __syncthreads();

        // ---- MMA: acc = As(64xKLEN) x Bs(192xKLEN)^T ----
        float acc[MM][MN][4];
#pragma unroll
        for (int im = 0; im < MM; im++)
#pragma unroll
            for (int in = 0; in < MN; in++)
#pragma unroll
                for (int q = 0; q < 4; q++) acc[im][in][q] = 0.f;

#pragma unroll
        for (int ks = 0; ks < KLEN / 8; ks++) {
            const int kk = ks * 8;
            unsigned af[MM][4], bf[MN][2];
#pragma unroll
            for (int im = 0; im < MM; im++) {
                ldsm_x4(af[im], aB + (unsigned)(im * 16 * LDSR + kk) * 4u);
                RNA4(af[im]);
            }
#pragma unroll
            for (int in = 0; in < MN; in++) {
                ldsm_x2(bf[in], bB + (unsigned)(in * 8 * LDSR + kk) * 4u);
                RNA2(bf[in]);
            }
#pragma unroll
            for (int im = 0; im < MM; im++)
#pragma unroll
                for (int in = 0; in < MN; in++)
                    mma8(acc[im][in], af[im], bf[in]);
        }

        // ---- write partials (parity buffer) ----
#pragma unroll
        for (int im = 0; im < MM; im++) {
            int row0 = wm * TM + im * 16 + g;
#pragma unroll
            for (int in = 0; in < MN; in++) {
                int col = bn + wn * TN + in * 8 + 2 * tg;
                float* c = acc[im][in];
                *(float2*)(C + (size_t)row0 * H3 + col) = make_float2(c[0], c[1]);
                *(float2*)(C + (size_t)(row0 + 8) * H3 + col) = make_float2(c[2], c[3]);
            }
        }

        // ---- barrier1 (global): all partials visible ----
        __syncthreads();
        if (tid == 0) {
            __threadfence();
            atomicAdd(&g_cnt[t], 1);
            while (((volatile int*)g_cnt)[t] < NBLK) {}
            __threadfence();
        }
        __syncthreads();

        // ---- gate (z-sliced): h_t cols [z*128, z*128+128), b in [bx*4, bx*4+4)
        float* hnew = hs + (size_t)t * B * H;
        for (int e = tid; e < 4 * KLEN; e += NT) {
            int b = bx * 4 + (e >> 7);
            int j = (z << 7) + (e & 127);
            float hr = b_hh_[j], hz = b_hh_[H + j], hn = b_hh_[2 * H + j];
#pragma unroll
            for (int s = 0; s < KSPLIT; s++) {
                const float* p = pbuf + (size_t)s * B * H3 + (size_t)b * H3;
                hr += __ldcg(p + j);
                hz += __ldcg(p + H + j);
                hn += __ldcg(p + 2 * H + j);
            }
            const float* gib = gi + (size_t)b * H3;
            float ir = gib[j], iz = gib[H + j], in_ = gib[2 * H + j];
            float r = 1.f / (1.f + expf(-(ir + hr)));
            float z_ = 1.f / (1.f + expf(-(iz + hz)));
            float n = tanhf(in_ + r * hn);
            hnew[(size_t)b * H + j] = (1.f - z_) * n + z_ * __ldcg(hprev + (size_t)b * H + j);
        }

        // ---- barrier2 (z-group, 16 blocks): h z-slice visible for next A load
        if (t + 1 < T) {
            __syncthreads();
            if (tid == 0) {
                __threadfence();
                int* c2 = &g_cnt[T + t * KSPLIT + z];
                atomicAdd(c2, 1);
                while (*(volatile int*)c2 < ZBLK) {}
                __threadfence();
            }
            __syncthreads();
        }
    }
}

// ---------------- elementwise / attention kernels ----------------

// scores: grid (B, 7, 2); one s per warp (56 slots cover S=50), z selects 5
// decode steps. wq[5][H] + va_w staged in smem; u-loads software-pipelined.
__global__ void __launch_bounds__(256, 2)
k_scores(const float* __restrict__ wq, const float* __restrict__ uk,
         const float* __restrict__ va_w, const float* __restrict__ va_b,
         float* __restrict__ scores) {
    constexpr int TB = T / 2;     // 5 steps per block
    __shared__ float wqs[TB][H];  // 20 KB
    __shared__ float vas[H];      // 4 KB
    int b = blockIdx.x, th0 = blockIdx.z * TB;
    int tid = threadIdx.x;
    for (int i = tid; i < TB * H; i += 256) {
        wqs[0][i] = wq[(size_t)((i / H + th0) * B + b) * H + (i % H)];
    }
    for (int i = tid; i < H; i += 256) vas[i] = va_w[i];
    __syncthreads();

    int warp = tid >> 5, lane = tid & 31;
    int s = blockIdx.y * 8 + warp;
    if (s >= S) return;

    const float4* ukr = (const float4*)(uk + (size_t)(s * B + b) * H);
    float acc[TB];
#pragma unroll
    for (int t = 0; t < TB; t++) acc[t] = 0.f;

    float4 u = ukr[lane];   // prefetch iter 0
#pragma unroll
    for (int i = 0; i < H / 128; i++) {
        float4 un = (i + 1 < H / 128) ? ukr[lane + (i + 1) * 32] : u;  // prefetch next
        float4 v = *(const float4*)&vas[(lane + i * 32) * 4];
#pragma unroll
        for (int t = 0; t < TB; t++) {
            float4 w = *(const float4*)&wqs[t][(lane + i * 32) * 4];
            float a = acc[t];
            a = fmaf(v.x, tanha(w.x + u.x), a);
            a = fmaf(v.y, tanha(w.y + u.y), a);
            a = fmaf(v.z, tanha(w.z + u.z), a);
            a = fmaf(v.w, tanha(w.w + u.w), a);
            acc[t] = a;
        }
        u = un;
    }
    float vb = va_b[0];
#pragma unroll
    for (int t = 0; t < TB; t++) {
#pragma unroll
        for (int o = 16; o; o >>= 1) acc[t] += __shfl_xor_sync(0xffffffffu, acc[t], o);
        if (lane == 0) scores[(size_t)((th0 + t) * B + b) * S + s] = acc[t] + vb;
    }
}

// softmax (in-smem) + context + log_softmax + h_last copy: one block per b.
__global__ void k_context(const float* __restrict__ scores,
                          const float* __restrict__ enc,
                          const float* __restrict__ hs_last,
                          float* __restrict__ out, int do_hlast) {
    int b = blockIdx.x;
    int tid = threadIdx.x;
    int warp = tid >> 5, lane = tid & 31;
    __shared__ float w[T][S];
    __shared__ float red[8];

    for (int i = tid; i < T * S; i += 256) {
        int t = i / S, s = i % S;
        w[t][s] = scores[(size_t)(t * B + b) * S + s];
    }
    __syncthreads();

    for (int t = warp; t < T; t += 8) {
        float v0 = (lane < S) ? w[t][lane] : -1e30f;
        float v1 = (lane + 32 < S) ? w[t][lane + 32] : -1e30f;
        float m = fmaxf(v0, v1);
#pragma unroll
        for (int o = 16; o; o >>= 1) m = fmaxf(m, __shfl_xor_sync(0xffffffffu, m, o));
        float e0 = (lane < S) ? expf(v0 - m) : 0.f;
        float e1 = (lane + 32 < S) ? expf(v1 - m) : 0.f;
        float sum = e0 + e1;
#pragma unroll
        for (int o = 16; o; o >>= 1) sum += __shfl_xor_sync(0xffffffffu, sum, o);
        float inv = 1.f / sum;
        if (lane < S) w[t][lane] = e0 * inv;
        if (lane + 32 < S) w[t][lane + 32] = e1 * inv;
    }
    __syncthreads();

    float c[T][8];
#pragma unroll
    for (int t = 0; t < T; t++)
#pragma unroll
        for (int i = 0; i < 8; i++) c[t][i] = 0.f;

    for (int s = 0; s < S; s++) {
        const float* kr = enc + (size_t)(s * B + b) * H2;
        float4 k0 = *(const float4*)(kr + tid * 8);
        float4 k1 = *(const float4*)(kr + tid * 8 + 4);
        float kv[8] = {k0.x, k0.y, k0.z, k0.w, k1.x, k1.y, k1.z, k1.w};
#pragma unroll
        for (int t = 0; t < T; t++) {
            float ws = w[t][s];
#pragma unroll
            for (int i = 0; i < 8; i++) c[t][i] = fmaf(ws, kv[i], c[t][i]);
        }
    }

    for (int t = 0; t < T; t++) {
        float m = c[t][0];
#pragma unroll
        for (int i = 1; i < 8; i++) m = fmaxf(m, c[t][i]);
#pragma unroll
        for (int o = 16; o; o >>= 1) m = fmaxf(m, __shfl_xor_sync(0xffffffffu, m, o));
        if (lane == 0) red[warp] = m;
        __syncthreads();
        if (tid == 0) {
            float mm = red[0];
            for (int i = 1; i < 8; i++) mm = fmaxf(mm, red[i]);
            red[0] = mm;
        }
        __syncthreads();
        m = red[0];
        __syncthreads();

        float sum = 0.f;
#pragma unroll
        for (int i = 0; i < 8; i++) sum += expf(c[t][i] - m);
#pragma unroll
        for (int o = 16; o; o >>= 1) sum += __shfl_xor_sync(0xffffffffu, sum, o);
        if (lane == 0) red[warp] = sum;
        __syncthreads();
        if (tid == 0) {
            float ss = 0.f;
            for (int i = 1; i < 8; i++) ss += red[i];
            red[0] += ss;
        }
        __syncthreads();
        float lse = m + logf(red[0]);
        __syncthreads();

        float* o_ = out + (size_t)(b * T + t) * H2 + tid * 8;
        *(float4*)o_ = make_float4(c[t][0] - lse, c[t][1] - lse, c[t][2] - lse, c[t][3] - lse);
        *(float4*)(o_ + 4) = make_float4(c[t][4] - lse, c[t][5] - lse, c[t][6] - lse, c[t][7] - lse);
    }

    if (do_hlast) {
        float* dst = out + (size_t)B * T * H2 + (size_t)b * H;
        const float* src = hs_last + (size_t)b * H;
#pragma unroll
        for (int i = 0; i < H / 256; i++) dst[tid + i * 256] = src[tid + i * 256];
    }
}

// ---------------- launch (single default stream, deterministic) -------------
extern "C" void kernel_launch(void* const* d_in, const int* in_sizes, int n_in,
                              void* d_out, int out_size) {
    const float* enc    = (const float*)d_in[0];
    const float* hidden = (const float*)d_in[1];
    const int*   target = (const int*)d_in[2];
    const float* emb    = (const float*)d_in[3];
    const float* w_ih   = (const float*)d_in[4];
    const float* w_hh   = (const float*)d_in[5];
    const float* b_ih   = (const float*)d_in[6];
    const float* b_hh   = (const float*)d_in[7];
    const float* wa_w   = (const float*)d_in[8];
    const float* wa_b   = (const float*)d_in[9];
    const float* ua_w   = (const float*)d_in[10];
    const float* ua_b   = (const float*)d_in[11];
    const float* va_w   = (const float*)d_in[12];
    const float* va_b   = (const float*)d_in[13];
    float* out = (float*)d_out;

    float *gi, *ghp, *hs, *uk, *wq, *sc;
    cudaGetSymbolAddress((void**)&gi, g_gi);
    cudaGetSymbolAddress((void**)&ghp, g_ghp);
    cudaGetSymbolAddress((void**)&hs, g_hs);
    cudaGetSymbolAddress((void**)&uk, g_uk);
    cudaGetSymbolAddress((void**)&wq, g_wq);
    cudaGetSymbolAddress((void**)&sc, g_sc);

    constexpr int LDSR = 36;
    const int smem_big = 2 * (128 + 128) * LDSR * 4;        // 73728 B
    const int smem_gru = (192 + 64) * (128 + 4) * 4;        // 135168 B
    cudaFuncSetAttribute((const void*)k_gemm_dual,
                         cudaFuncAttributeMaxDynamicSharedMemorySize, smem_big);
    cudaFuncSetAttribute((const void*)k_gemm_wq,
                         cudaFuncAttributeMaxDynamicSharedMemorySize, smem_big);
    cudaFuncSetAttribute((const void*)k_gru_all,
                         cudaFuncAttributeMaxDynamicSharedMemorySize, smem_gru);

    // uk (200 tiles) + gi (120 tiles) in one full-machine launch; also resets
    // the GRU barrier counters (block 0) before k_gru_all runs.
    k_gemm_dual<<<320, 256, smem_big>>>(enc, ua_w, ua_b, uk,
                                        emb, w_ih, b_ih, gi, target);

    // persistent GRU: all T steps, W_hh resident in smem (128 co-resident blocks)
    k_gru_all<<<dim3(H3 / 192, 1, KSPLIT), 256, smem_gru>>>(
        hidden, w_hh, gi, b_hh, ghp, hs);

    // wq = hs @ wa_w^T + wa_b   [640, 1024], K=1024
    k_gemm_wq<<<dim3(H / 128, (T * B) / 128), 256, smem_big>>>(hs, wa_w, wa_b, wq);

    // attention scores: one s per warp, T split in halves
    k_scores<<<dim3(B, 7, 2), 256>>>(wq, uk, va_w, va_b, sc);

    int do_hlast = (out_size >= B * T * H2 + B * H) ? 1 : 0;
    k_context<<<B, 256>>>(sc, enc, hs + (size_t)(T - 1) * B * H, out, do_hlast);
}

// round 16
// speedup vs baseline: 1.0312x; 1.0312x over previous
#include <cuda_runtime.h>
#include <math.h>

// Problem dims (fixed by the reference)
namespace cfg {
constexpr int V = 32000, E = 512, H = 1024, S = 50, B = 64, T = 10;
constexpr int H2 = 2 * H, H3 = 3 * H;
constexpr int KSPLIT = 8;   // K slices for the GRU (KLEN = 128)
}
using namespace cfg;

// ---------------- device scratch (no allocations allowed) ----------------
__device__ float g_gi[T * B * H3];         // emb[dec_in] @ w_ih^T + b_ih  [T*B, 3H]
__device__ float g_ghp[KSPLIT * B * H3];   // split-K partials of h @ w_hh^T
__device__ float g_hs[T * B * H];          // GRU hidden states    [T, B, H]
__device__ float g_uk[B * S * H];          // enc @ ua_w^T + ua_b, rows in (s*B+b) order
__device__ float g_wq[T * B * H];          // hs @ wa_w^T + wa_b   [T*B, H]
__device__ float g_sc[T * B * S];          // raw scores           [T*B, S]
__device__ int   g_cnt[2 * T];             // persistent-kernel barrier counters

// ---------------- small intrinsics ----------------
__device__ __forceinline__ float tanha(float x) {
    float y;
    asm("tanh.approx.f32 %0, %1;" : "=f"(y) : "f"(x));
    return y;
}
__device__ __forceinline__ void mma8(float* c, const unsigned* a, const unsigned* b) {
    asm volatile(
        "mma.sync.aligned.m16n8k8.row.col.f32.tf32.tf32.f32 "
        "{%0,%1,%2,%3}, {%4,%5,%6,%7}, {%8,%9}, {%0,%1,%2,%3};"
        : "+f"(c[0]), "+f"(c[1]), "+f"(c[2]), "+f"(c[3])
        : "r"(a[0]), "r"(a[1]), "r"(a[2]), "r"(a[3]), "r"(b[0]), "r"(b[1]));
}
__device__ __forceinline__ void cp16(float* smem_dst, const float* gptr) {
    unsigned s = (unsigned)__cvta_generic_to_shared(smem_dst);
    asm volatile("cp.async.cg.shared.global [%0], [%1], 16;\n" :: "r"(s), "l"(gptr));
}
// ldmatrix on 32-bit data: m8n8.b16 over 8x(16B rows) => 8x4 b32 matrix;
// thread t receives b32 element (row t/4, col t%4) == tf32 frag layout.
__device__ __forceinline__ void ldsm_x4(unsigned* r, unsigned addr) {
    asm volatile("ldmatrix.sync.aligned.m8n8.x4.shared.b16 {%0,%1,%2,%3}, [%4];"
                 : "=r"(r[0]), "=r"(r[1]), "=r"(r[2]), "=r"(r[3]) : "r"(addr));
}
// RNA rounding for tf32 applied on the fragment register (same numerics as
// cvt.rna: +half-ulp of the 10-bit mantissa before the mma truncates).
#define RNA4(f) { f[0] += 0x1000u; f[1] += 0x1000u; f[2] += 0x1000u; f[3] += 0x1000u; }

// A-fragment lane base: x4 covering one 16-row m-tile, cols kk..kk+7.
//   lanes 0-7:(rw,0) 8-15:(8+rw,0) 16-23:(rw,4) 24-31:(8+rw,4)  [proven mapping]
// B-fragment PAIR lane base: x4 covering n-tiles (2p,2p+1), cols kk..kk+7:
//   lanes 0-7:(rw,0) 8-15:(rw,4) 16-23:(8+rw,0) 24-31:(8+rw,4)
//   -> r0,r1 = n-tile 2p {kk,kk+4}; r2,r3 = n-tile 2p+1 {kk,kk+4}.

// ============ unified 128x128 tf32 GEMM body =========
// C[m][n] = bias[n] + sum_k A[m][k]*W[n][k]; 256 threads; smem = 2*(128+128)*36*4.
// gather: row m of A is emb[dec_in(m)], dec_in(m) = (t==0?0:target[b*T+t-1]).
__device__ __forceinline__ void gemm128_body(
    const float* __restrict__ A, const float* __restrict__ W,
    const float* __restrict__ bias, float* __restrict__ C,
    int N, int K, int bm, int bn, bool gather, const int* __restrict__ target,
    float* sm) {
    constexpr int BM = 128, BN = 128, WM = 4, WN = 2;
    constexpr int BK = 32, NT = 256;
    constexpr int TM = BM / WM, TN = BN / WN;   // 32, 64
    constexpr int MM = TM / 16, MN = TN / 8;    // 2, 8
    constexpr int LDSR = BK + 4;                // 36 floats = 144 B rows
    constexpr int A_LD = 4, B_LD = 4;

    float* Asm = sm;                      // [2][BM*LDSR]
    float* Bsm = sm + 2 * BM * LDSR;      // [2][BN*LDSR]

    const int tid = threadIdx.x;
    const int warp = tid >> 5, lane = tid & 31;
    const int wm = warp / WN, wn = warp % WN;
    const int g = lane >> 2, tg = lane & 3;

    const float* abase[A_LD];
    const float* bbase[B_LD];
    int aoff[A_LD], boff[B_LD];
#pragma unroll
    for (int i = 0; i < A_LD; i++) {
        int idx = tid + i * NT;
        int r = idx >> 3, kq = idx & 7;
        int m = bm + r;
        const float* ar;
        if (gather) {
            int t = m / B, b = m % B;
            int tok = (t == 0) ? 0 : target[b * T + (t - 1)];
            ar = A + (size_t)tok * K;
        } else {
            ar = A + (size_t)m * K;
        }
        abase[i] = ar + kq * 4;
        aoff[i] = r * LDSR + kq * 4;
    }
#pragma unroll
    for (int i = 0; i < B_LD; i++) {
        int idx = tid + i * NT;
        int r = idx >> 3, kq = idx & 7;
        bbase[i] = W + (size_t)(bn + r) * K + kq * 4;
        boff[i] = r * LDSR + kq * 4;
    }

    const int rw = lane & 7;
    // A x4 base (proven): row = wm*TM + rw + 8*(lane>>3 & 1), col-half = (lane>>4)*4
    const unsigned aB = (unsigned)__cvta_generic_to_shared(Asm) +
        ((unsigned)((wm * TM + rw + 8 * ((lane >> 3) & 1)) * LDSR + 4 * (lane >> 4))) * 4u;
    // B pair-x4 base: row = wn*TN + rw + 8*(lane>>4), col-half = ((lane>>3)&1)*4
    const unsigned bB = (unsigned)__cvta_generic_to_shared(Bsm) +
        ((unsigned)((wn * TN + rw + 8 * (lane >> 4)) * LDSR + 4 * ((lane >> 3) & 1))) * 4u;

    float acc[MM][MN][4];
#pragma unroll
    for (int im = 0; im < MM; im++)
#pragma unroll
        for (int in = 0; in < MN; in++)
#pragma unroll
            for (int q = 0; q < 4; q++) acc[im][in][q] = 0.f;

    auto issue = [&](int k0, int buf) {
        float* as = Asm + buf * BM * LDSR;
        float* bs = Bsm + buf * BN * LDSR;
#pragma unroll
        for (int i = 0; i < A_LD; i++) cp16(as + aoff[i], abase[i] + k0);
#pragma unroll
        for (int i = 0; i < B_LD; i++) cp16(bs + boff[i], bbase[i] + k0);
        asm volatile("cp.async.commit_group;\n" ::);
    };

    issue(0, 0);
    const int KT = K / BK;
    for (int kt = 0; kt < KT; kt++) {
        if (kt + 1 < KT) {
            issue((kt + 1) * BK, (kt + 1) & 1);
            asm volatile("cp.async.wait_group 1;\n" ::);
        } else {
            asm volatile("cp.async.wait_group 0;\n" ::);
        }
        __syncthreads();

        const unsigned aBuf = aB + (unsigned)((kt & 1) * BM * LDSR) * 4u;
        const unsigned bBuf = bB + (unsigned)((kt & 1) * BN * LDSR) * 4u;
#pragma unroll
        for (int ks = 0; ks < 4; ks++) {
            const int kk = ks * 8;
            unsigned af[MM][4], bf[MN / 2][4];
#pragma unroll
            for (int im = 0; im < MM; im++) {
                ldsm_x4(af[im], aBuf + (unsigned)(im * 16 * LDSR + kk) * 4u);
                RNA4(af[im]);
            }
#pragma unroll
            for (int p = 0; p < MN / 2; p++) {
                ldsm_x4(bf[p], bBuf + (unsigned)(p * 16 * LDSR + kk) * 4u);
                RNA4(bf[p]);
            }
#pragma unroll
            for (int im = 0; im < MM; im++)
#pragma unroll
                for (int p = 0; p < MN / 2; p++) {
                    mma8(acc[im][2 * p], af[im], bf[p]);
                    mma8(acc[im][2 * p + 1], af[im], bf[p] + 2);
                }
        }
        __syncthreads();
    }

#pragma unroll
    for (int im = 0; im < MM; im++) {
        int row0 = bm + wm * TM + im * 16 + g;
#pragma unroll
        for (int in = 0; in < MN; in++) {
            int col = bn + wn * TN + in * 8 + 2 * tg;
            float2 bb = *(const float2*)(bias + col);
            float* c = acc[im][in];
            *(float2*)(C + (size_t)row0 * N + col) = make_float2(c[0] + bb.x, c[1] + bb.y);
            *(float2*)(C + (size_t)(row0 + 8) * N + col) = make_float2(c[2] + bb.x, c[3] + bb.y);
        }
    }
}

// ---- dual GEMM: blocks 0..199 compute uk, 200..319 compute gi (one launch) --
// Also resets the GRU barrier counters (block 0) — runs before k_gru_all.
__global__ void __launch_bounds__(256, 2)
k_gemm_dual(const float* __restrict__ enc, const float* __restrict__ ua_w,
            const float* __restrict__ ua_b, float* __restrict__ uk,
            const float* __restrict__ emb, const float* __restrict__ w_ih,
            const float* __restrict__ b_ih, float* __restrict__ gi,
            const int* __restrict__ target) {
    extern __shared__ float sm[];
    const int bid = blockIdx.x;
    if (bid == 0 && threadIdx.x < 2 * T) g_cnt[threadIdx.x] = 0;

    if (bid < 200) {
        // uk tile: M=3200 (25), N=1024 (8), K=2048
        int bx = bid & 7, by = bid >> 3;
        gemm128_body(enc, ua_w, ua_b, uk, H, H2, by * 128, bx * 128,
                     false, nullptr, sm);
    } else {
        // gi tile: M=640 (5), N=3072 (24), K=512, gathered A
        int idx = bid - 200;
        int bx = idx % 24, by = idx / 24;
        gemm128_body(emb, w_ih, b_ih, gi, H3, E, by * 128, bx * 128,
                     true, target, sm);
    }
}

// ---- wq GEMM (stand-alone, same proven body) --------------------------------
__global__ void __launch_bounds__(256, 2)
k_gemm_wq(const float* __restrict__ A, const float* __restrict__ W,
          const float* __restrict__ bias, float* __restrict__ C) {
    extern __shared__ float sm[];
    gemm128_body(A, W, bias, C, H, H, blockIdx.y * 128, blockIdx.x * 128,
                 false, nullptr, sm);
}

// ---------------- persistent GRU, weight-resident in smem -------------------
// Grid (16,1,8) = 128 blocks, 1 block/SM (smem) -> co-resident; counter barrier.
__global__ void __launch_bounds__(256)
k_gru_all(const float* __restrict__ hidden, const float* __restrict__ whh,
          const float* __restrict__ gi_all, const float* __restrict__ b_hh_,
          float* __restrict__ part, float* __restrict__ hs) {
    constexpr int BM = 64, BN = 192, WM = 2, WN = 4;
    constexpr int NT = 256;
    constexpr int TM = BM / WM, TN = BN / WN;   // 32, 48
    constexpr int MM = TM / 16, MN = TN / 8;    // 2, 6
    constexpr int KLEN = H / KSPLIT;            // 128
    constexpr int LDSR = KLEN + 4;              // 132 floats = 528 B rows
    constexpr int NBLK = (H3 / BN) * KSPLIT;    // 128
    constexpr int A_CP = BM * (KLEN / 4) / NT;  // 8
    constexpr int B_CP = BN * (KLEN / 4) / NT;  // 24

    extern __shared__ float sm[];
    float* Bs = sm;                 // [BN][LDSR]  weights, resident
    float* As = sm + BN * LDSR;     // [BM][LDSR]  hprev slice, per step

    const int tid = threadIdx.x;
    const int warp = tid >> 5, lane = tid & 31;
    const int wm = warp / WN, wn = warp % WN;
    const int g = lane >> 2, tg = lane & 3;
    const int bn = blockIdx.x * BN;
    const int z = blockIdx.z;
    const int kstart = z * KLEN;
    float* C = part + (size_t)z * B * H3;

    // ---- load W_hh tile once (192 x 128 floats) ----
#pragma unroll
    for (int i = 0; i < B_CP; i++) {
        int idx = tid + i * NT;
        int r = idx >> 5, kq = idx & 31;
        cp16(Bs + r * LDSR + kq * 4, whh + (size_t)(bn + r) * H + kstart + kq * 4);
    }
    asm volatile("cp.async.commit_group;\n" ::);

    const int rw = lane & 7;
    const unsigned aB = (unsigned)__cvta_generic_to_shared(As) +
        ((unsigned)((wm * TM + rw + 8 * ((lane >> 3) & 1)) * LDSR + 4 * (lane >> 4))) * 4u;
    const unsigned bB = (unsigned)__cvta_generic_to_shared(Bs) +
        ((unsigned)((wn * TN + rw + 8 * (lane >> 4)) * LDSR + 4 * ((lane >> 3) & 1))) * 4u;

    const int gtid = (z * gridDim.x + blockIdx.x) * NT + tid;
    constexpr int GSTRIDE = NBLK * NT;   // 32768

    for (int t = 0; t < T; t++) {
        const float* hprev = (t == 0) ? hidden : hs + (size_t)(t - 1) * B * H;
        const float* gi = gi_all + (size_t)t * B * H3;

        // ---- load hprev slice (64 x 128 floats) ----
#pragma unroll
        for (int i = 0; i < A_CP; i++) {
            int idx = tid + i * NT;
            int r = idx >> 5, kq = idx & 31;
            cp16(As + r * LDSR + kq * 4, hprev + (size_t)r * H + kstart + kq * 4);
        }
        asm volatile("cp.async.commit_group;\n" ::);
        asm volatile("cp.async.wait_group 0;\n" ::);
        __syncthreads();

        // ---- MMA: acc = As(64xKLEN) x Bs(192xKLEN)^T ----
        float acc[MM][MN][4];
#pragma unroll
        for (int im = 0; im < MM; im++)
#pragma unroll
            for (int in = 0; in < MN; in++)
#pragma unroll
                for (int q = 0; q < 4; q++) acc[im][in][q] = 0.f;

#pragma unroll
        for (int ks = 0; ks < KLEN / 8; ks++) {
            const int kk = ks * 8;
            unsigned af[MM][4], bf[MN / 2][4];
#pragma unroll
            for (int im = 0; im < MM; im++) {
                ldsm_x4(af[im], aB + (unsigned)(im * 16 * LDSR + kk) * 4u);
                RNA4(af[im]);
            }
#pragma unroll
            for (int p = 0; p < MN / 2; p++) {
                ldsm_x4(bf[p], bB + (unsigned)(p * 16 * LDSR + kk) * 4u);
                RNA4(bf[p]);
            }
#pragma unroll
            for (int im = 0; im < MM; im++)
#pragma unroll
                for (int p = 0; p < MN / 2; p++) {
                    mma8(acc[im][2 * p], af[im], bf[p]);
                    mma8(acc[im][2 * p + 1], af[im], bf[p] + 2);
                }
        }

        // ---- write partials ----
#pragma unroll
        for (int im = 0; im < MM; im++) {
            int row0 = wm * TM + im * 16 + g;
#pragma unroll
            for (int in = 0; in < MN; in++) {
                int col = bn + wn * TN + in * 8 + 2 * tg;
                float* c = acc[im][in];
                *(float2*)(C + (size_t)row0 * H3 + col) = make_float2(c[0], c[1]);
                *(float2*)(C + (size_t)(row0 + 8) * H3 + col) = make_float2(c[2], c[3]);
            }
        }

        // ---- barrier: partials visible ----
        __syncthreads();
        if (tid == 0) {
            __threadfence();
            atomicAdd(&g_cnt[2 * t], 1);
            while (((volatile int*)g_cnt)[2 * t] < NBLK) {}
            __threadfence();
        }
        __syncthreads();

        // ---- gate: h_t = (1-z)*tanh(in + r*hn) + z*h ----
        float* hnew = hs + (size_t)t * B * H;
        for (int idx = gtid; idx < B * H; idx += GSTRIDE) {
            int b = idx / H, j = idx % H;
            float hr = b_hh_[j], hz = b_hh_[H + j], hn = b_hh_[2 * H + j];
#pragma unroll
            for (int s = 0; s < KSPLIT; s++) {
                const float* p = part + (size_t)s * B * H3 + (size_t)b * H3;
                hr += __ldcg(p + j);
                hz += __ldcg(p + H + j);
                hn += __ldcg(p + 2 * H + j);
            }
            const float* gib = gi + (size_t)b * H3;
            float ir = gib[j], iz = gib[H + j], in_ = gib[2 * H + j];
            float r = 1.f / (1.f + expf(-(ir + hr)));
            float z_ = 1.f / (1.f + expf(-(iz + hz)));
            float n = tanhf(in_ + r * hn);
            hnew[idx] = (1.f - z_) * n + z_ * __ldcg(hprev + idx);
        }

        // ---- barrier: h_t visible before next step's A load ----
        if (t + 1 < T) {
            __syncthreads();
            if (tid == 0) {
                __threadfence();
                atomicAdd(&g_cnt[2 * t + 1], 1);
                while (((volatile int*)g_cnt)[2 * t + 1] < NBLK) {}
                __threadfence();
            }
            __syncthreads();
        }
    }
}

// ---------------- elementwise / attention kernels ----------------

// scores: grid (B, 7, 2); one s per warp (56 slots cover S=50), z selects 5
// decode steps. wq[5][H] + va_w staged in smem (24 KB -> multi-block/SM).
__global__ void __launch_bounds__(256, 2)
k_scores(const float* __restrict__ wq, const float* __restrict__ uk,
         const float* __restrict__ va_w, const float* __restrict__ va_b,
         float* __restrict__ scores) {
    constexpr int TB = T / 2;     // 5 steps per block
    __shared__ float wqs[TB][H];  // 20 KB
    __shared__ float vas[H];      // 4 KB
    int b = blockIdx.x, th0 = blockIdx.z * TB;
    int tid = threadIdx.x;
    for (int i = tid; i < TB * H; i += 256) {
        wqs[0][i] = wq[(size_t)((i / H + th0) * B + b) * H + (i % H)];
    }
    for (int i = tid; i < H; i += 256) vas[i] = va_w[i];
    __syncthreads();

    int warp = tid >> 5, lane = tid & 31;
    int s = blockIdx.y * 8 + warp;
    if (s >= S) return;

    const float4* ukr = (const float4*)(uk + (size_t)(s * B + b) * H);
    float acc[TB];
#pragma unroll
    for (int t = 0; t < TB; t++) acc[t] = 0.f;
#pragma unroll
    for (int i = 0; i < H / 128; i++) {
        float4 u = ukr[lane + i * 32];
        float4 v = *(const float4*)&vas[(lane + i * 32) * 4];
#pragma unroll
        for (int t = 0; t < TB; t++) {
            float4 w = *(const float4*)&wqs[t][(lane + i * 32) * 4];
            float a = acc[t];
            a = fmaf(v.x, tanha(w.x + u.x), a);
            a = fmaf(v.y, tanha(w.y + u.y), a);
            a = fmaf(v.z, tanha(w.z + u.z), a);
            a = fmaf(v.w, tanha(w.w + u.w), a);
            acc[t] = a;
        }
    }
    float vb = va_b[0];
#pragma unroll
    for (int t = 0; t < TB; t++) {
#pragma unroll
        for (int o = 16; o; o >>= 1) acc[t] += __shfl_xor_sync(0xffffffffu, acc[t], o);
        if (lane == 0) scores[(size_t)((th0 + t) * B + b) * S + s] = acc[t] + vb;
    }
}

// softmax (in-smem) + context + log_softmax + h_last copy: one block per b.
__global__ void k_context(const float* __restrict__ scores,
                          const float* __restrict__ enc,
                          const float* __restrict__ hs_last,
                          float* __restrict__ out, int do_hlast) {
    int b = blockIdx.x;
    int tid = threadIdx.x;
    int warp = tid >> 5, lane = tid & 31;
    __shared__ float w[T][S];
    __shared__ float red[8];

    for (int i = tid; i < T * S; i += 256) {
        int t = i / S, s = i % S;
        w[t][s] = scores[(size_t)(t * B + b) * S + s];
    }
    __syncthreads();

    for (int t = warp; t < T; t += 8) {
        float v0 = (lane < S) ? w[t][lane] : -1e30f;
        float v1 = (lane + 32 < S) ? w[t][lane + 32] : -1e30f;
        float m = fmaxf(v0, v1);
#pragma unroll
        for (int o = 16; o; o >>= 1) m = fmaxf(m, __shfl_xor_sync(0xffffffffu, m, o));
        float e0 = (lane < S) ? expf(v0 - m) : 0.f;
        float e1 = (lane + 32 < S) ? expf(v1 - m) : 0.f;
        float sum = e0 + e1;
#pragma unroll
        for (int o = 16; o; o >>= 1) sum += __shfl_xor_sync(0xffffffffu, sum, o);
        float inv = 1.f / sum;
        if (lane < S) w[t][lane] = e0 * inv;
        if (lane + 32 < S) w[t][lane + 32] = e1 * inv;
    }
    __syncthreads();

    float c[T][8];
#pragma unroll
    for (int t = 0; t < T; t++)
#pragma unroll
        for (int i = 0; i < 8; i++) c[t][i] = 0.f;

    for (int s = 0; s < S; s++) {
        const float* kr = enc + (size_t)(s * B + b) * H2;
        float4 k0 = *(const float4*)(kr + tid * 8);
        float4 k1 = *(const float4*)(kr + tid * 8 + 4);
        float kv[8] = {k0.x, k0.y, k0.z, k0.w, k1.x, k1.y, k1.z, k1.w};
#pragma unroll
        for (int t = 0; t < T; t++) {
            float ws = w[t][s];
#pragma unroll
            for (int i = 0; i < 8; i++) c[t][i] = fmaf(ws, kv[i], c[t][i]);
        }
    }

    for (int t = 0; t < T; t++) {
        float m = c[t][0];
#pragma unroll
        for (int i = 1; i < 8; i++) m = fmaxf(m, c[t][i]);
#pragma unroll
        for (int o = 16; o; o >>= 1) m = fmaxf(m, __shfl_xor_sync(0xffffffffu, m, o));
        if (lane == 0) red[warp] = m;
        __syncthreads();
        if (tid == 0) {
            float mm = red[0];
            for (int i = 1; i < 8; i++) mm = fmaxf(mm, red[i]);
            red[0] = mm;
        }
        __syncthreads();
        m = red[0];
        __syncthreads();

        float sum = 0.f;
#pragma unroll
        for (int i = 0; i < 8; i++) sum += expf(c[t][i] - m);
#pragma unroll
        for (int o = 16; o; o >>= 1) sum += __shfl_xor_sync(0xffffffffu, sum, o);
        if (lane == 0) red[warp] = sum;
        __syncthreads();
        if (tid == 0) {
            float ss = 0.f;
            for (int i = 1; i < 8; i++) ss += red[i];
            red[0] += ss;
        }
        __syncthreads();
        float lse = m + logf(red[0]);
        __syncthreads();

        float* o_ = out + (size_t)(b * T + t) * H2 + tid * 8;
        *(float4*)o_ = make_float4(c[t][0] - lse, c[t][1] - lse, c[t][2] - lse, c[t][3] - lse);
        *(float4*)(o_ + 4) = make_float4(c[t][4] - lse, c[t][5] - lse, c[t][6] - lse, c[t][7] - lse);
    }

    if (do_hlast) {
        float* dst = out + (size_t)B * T * H2 + (size_t)b * H;
        const float* src = hs_last + (size_t)b * H;
#pragma unroll
        for (int i = 0; i < H / 256; i++) dst[tid + i * 256] = src[tid + i * 256];
    }
}

// ---------------- launch (single default stream, deterministic) -------------
extern "C" void kernel_launch(void* const* d_in, const int* in_sizes, int n_in,
                              void* d_out, int out_size) {
    const float* enc    = (const float*)d_in[0];
    const float* hidden = (const float*)d_in[1];
    const int*   target = (const int*)d_in[2];
    const float* emb    = (const float*)d_in[3];
    const float* w_ih   = (const float*)d_in[4];
    const float* w_hh   = (const float*)d_in[5];
    const float* b_ih   = (const float*)d_in[6];
    const float* b_hh   = (const float*)d_in[7];
    const float* wa_w   = (const float*)d_in[8];
    const float* wa_b   = (const float*)d_in[9];
    const float* ua_w   = (const float*)d_in[10];
    const float* ua_b   = (const float*)d_in[11];
    const float* va_w   = (const float*)d_in[12];
    const float* va_b   = (const float*)d_in[13];
    float* out = (float*)d_out;

    float *gi, *ghp, *hs, *uk, *wq, *sc;
    cudaGetSymbolAddress((void**)&gi, g_gi);
    cudaGetSymbolAddress((void**)&ghp, g_ghp);
    cudaGetSymbolAddress((void**)&hs, g_hs);
    cudaGetSymbolAddress((void**)&uk, g_uk);
    cudaGetSymbolAddress((void**)&wq, g_wq);
    cudaGetSymbolAddress((void**)&sc, g_sc);

    constexpr int LDSR = 36;
    const int smem_big = 2 * (128 + 128) * LDSR * 4;        // 73728 B
    const int smem_gru = (192 + 64) * (128 + 4) * 4;        // 135168 B
    cudaFuncSetAttribute((const void*)k_gemm_dual,
                         cudaFuncAttributeMaxDynamicSharedMemorySize, smem_big);
    cudaFuncSetAttribute((const void*)k_gemm_wq,
                         cudaFuncAttributeMaxDynamicSharedMemorySize, smem_big);
    cudaFuncSetAttribute((const void*)k_gru_all,
                         cudaFuncAttributeMaxDynamicSharedMemorySize, smem_gru);

    // uk (200 tiles) + gi (120 tiles) in one full-machine launch; also resets
    // the GRU barrier counters (block 0) before k_gru_all runs.
    k_gemm_dual<<<320, 256, smem_big>>>(enc, ua_w, ua_b, uk,
                                        emb, w_ih, b_ih, gi, target);

    // persistent GRU: all T steps, W_hh resident in smem (128 co-resident blocks)
    k_gru_all<<<dim3(H3 / 192, 1, KSPLIT), 256, smem_gru>>>(
        hidden, w_hh, gi, b_hh, ghp, hs);

    // wq = hs @ wa_w^T + wa_b   [640, 1024], K=1024
    k_gemm_wq<<<dim3(H / 128, (T * B) / 128), 256, smem_big>>>(hs, wa_w, wa_b, wq);

    // attention scores: one s per warp, T split in halves
    k_scores<<<dim3(B, 7, 2), 256>>>(wq, uk, va_w, va_b, sc);

    int do_hlast = (out_size >= B * T * H2 + B * H) ? 1 : 0;
    k_context<<<B, 256>>>(sc, enc, hs + (size_t)(T - 1) * B * H, out, do_hlast);
}

// round 17
// speedup vs baseline: 1.0413x; 1.0098x over previous
#include <cuda_runtime.h>
#include <math.h>

// Problem dims (fixed by the reference)
namespace cfg {
constexpr int V = 32000, E = 512, H = 1024, S = 50, B = 64, T = 10;
constexpr int H2 = 2 * H, H3 = 3 * H;
constexpr int KSPLIT = 8;   // K slices for the GRU (KLEN = 128)
}
using namespace cfg;

// ---------------- device scratch (no allocations allowed) ----------------
__device__ float g_gi[T * B * H3];         // emb[dec_in] @ w_ih^T + b_ih  [T*B, 3H]
__device__ float g_ghp[KSPLIT * B * H3];   // split-K partials of h @ w_hh^T
__device__ float g_hs[T * B * H];          // GRU hidden states    [T, B, H]
__device__ float g_uk[B * S * H];          // enc @ ua_w^T + ua_b, rows in (s*B+b) order
__device__ float g_wq[T * B * H];          // hs @ wa_w^T + wa_b   [T*B, H]
__device__ float g_sc[T * B * S];          // raw scores           [T*B, S]
__device__ int   g_cnt[2 * T];             // persistent-kernel barrier counters

// ---------------- small intrinsics ----------------
__device__ __forceinline__ float tanha(float x) {
    float y;
    asm("tanh.approx.f32 %0, %1;" : "=f"(y) : "f"(x));
    return y;
}
__device__ __forceinline__ void mma8(float* c, const unsigned* a, const unsigned* b) {
    asm volatile(
        "mma.sync.aligned.m16n8k8.row.col.f32.tf32.tf32.f32 "
        "{%0,%1,%2,%3}, {%4,%5,%6,%7}, {%8,%9}, {%0,%1,%2,%3};"
        : "+f"(c[0]), "+f"(c[1]), "+f"(c[2]), "+f"(c[3])
        : "r"(a[0]), "r"(a[1]), "r"(a[2]), "r"(a[3]), "r"(b[0]), "r"(b[1]));
}
__device__ __forceinline__ void cp16(float* smem_dst, const float* gptr) {
    unsigned s = (unsigned)__cvta_generic_to_shared(smem_dst);
    asm volatile("cp.async.cg.shared.global [%0], [%1], 16;\n" :: "r"(s), "l"(gptr));
}
// ldmatrix on 32-bit data: m8n8.b16 over 8x(16B rows) => 8x4 b32 matrix;
// thread t receives b32 element (row t/4, col t%4) == tf32 frag layout.
__device__ __forceinline__ void ldsm_x4(unsigned* r, unsigned addr) {
    asm volatile("ldmatrix.sync.aligned.m8n8.x4.shared.b16 {%0,%1,%2,%3}, [%4];"
                 : "=r"(r[0]), "=r"(r[1]), "=r"(r[2]), "=r"(r[3]) : "r"(addr));
}
// RNA rounding for tf32 applied on the fragment register (same numerics as
// cvt.rna: +half-ulp of the 10-bit mantissa before the mma truncates).
#define RNA4(f) { f[0] += 0x1000u; f[1] += 0x1000u; f[2] += 0x1000u; f[3] += 0x1000u; }

// A-fragment lane base: x4 covering one 16-row m-tile, cols kk..kk+7.
//   lanes 0-7:(rw,0) 8-15:(8+rw,0) 16-23:(rw,4) 24-31:(8+rw,4)  [proven mapping]
// B-fragment PAIR lane base: x4 covering n-tiles (2p,2p+1), cols kk..kk+7:
//   lanes 0-7:(rw,0) 8-15:(rw,4) 16-23:(8+rw,0) 24-31:(8+rw,4)
//   -> r0,r1 = n-tile 2p {kk,kk+4}; r2,r3 = n-tile 2p+1 {kk,kk+4}.

// ============ unified 128x128 tf32 GEMM body =========
// C[m][n] = bias[n] + sum_k A[m][k]*W[n][k]; 256 threads; smem = 2*(128+128)*36*4.
// gather: row m of A is emb[dec_in(m)], dec_in(m) = (t==0?0:target[b*T+t-1]).
__device__ __forceinline__ void gemm128_body(
    const float* __restrict__ A, const float* __restrict__ W,
    const float* __restrict__ bias, float* __restrict__ C,
    int N, int K, int bm, int bn, bool gather, const int* __restrict__ target,
    float* sm) {
    constexpr int BM = 128, BN = 128, WM = 4, WN = 2;
    constexpr int BK = 32, NT = 256;
    constexpr int TM = BM / WM, TN = BN / WN;   // 32, 64
    constexpr int MM = TM / 16, MN = TN / 8;    // 2, 8
    constexpr int LDSR = BK + 4;                // 36 floats = 144 B rows
    constexpr int A_LD = 4, B_LD = 4;

    float* Asm = sm;                      // [2][BM*LDSR]
    float* Bsm = sm + 2 * BM * LDSR;      // [2][BN*LDSR]

    const int tid = threadIdx.x;
    const int warp = tid >> 5, lane = tid & 31;
    const int wm = warp / WN, wn = warp % WN;
    const int g = lane >> 2, tg = lane & 3;

    const float* abase[A_LD];
    const float* bbase[B_LD];
    int aoff[A_LD], boff[B_LD];
#pragma unroll
    for (int i = 0; i < A_LD; i++) {
        int idx = tid + i * NT;
        int r = idx >> 3, kq = idx & 7;
        int m = bm + r;
        const float* ar;
        if (gather) {
            int t = m / B, b = m % B;
            int tok = (t == 0) ? 0 : target[b * T + (t - 1)];
            ar = A + (size_t)tok * K;
        } else {
            ar = A + (size_t)m * K;
        }
        abase[i] = ar + kq * 4;
        aoff[i] = r * LDSR + kq * 4;
    }
#pragma unroll
    for (int i = 0; i < B_LD; i++) {
        int idx = tid + i * NT;
        int r = idx >> 3, kq = idx & 7;
        bbase[i] = W + (size_t)(bn + r) * K + kq * 4;
        boff[i] = r * LDSR + kq * 4;
    }

    const int rw = lane & 7;
    const unsigned aB = (unsigned)__cvta_generic_to_shared(Asm) +
        ((unsigned)((wm * TM + rw + 8 * ((lane >> 3) & 1)) * LDSR + 4 * (lane >> 4))) * 4u;
    const unsigned bB = (unsigned)__cvta_generic_to_shared(Bsm) +
        ((unsigned)((wn * TN + rw + 8 * (lane >> 4)) * LDSR + 4 * ((lane >> 3) & 1))) * 4u;

    float acc[MM][MN][4];
#pragma unroll
    for (int im = 0; im < MM; im++)
#pragma unroll
        for (int in = 0; in < MN; in++)
#pragma unroll
            for (int q = 0; q < 4; q++) acc[im][in][q] = 0.f;

    auto issue = [&](int k0, int buf) {
        float* as = Asm + buf * BM * LDSR;
        float* bs = Bsm + buf * BN * LDSR;
#pragma unroll
        for (int i = 0; i < A_LD; i++) cp16(as + aoff[i], abase[i] + k0);
#pragma unroll
        for (int i = 0; i < B_LD; i++) cp16(bs + boff[i], bbase[i] + k0);
        asm volatile("cp.async.commit_group;\n" ::);
    };

    issue(0, 0);
    const int KT = K / BK;
    for (int kt = 0; kt < KT; kt++) {
        if (kt + 1 < KT) {
            issue((kt + 1) * BK, (kt + 1) & 1);
            asm volatile("cp.async.wait_group 1;\n" ::);
        } else {
            asm volatile("cp.async.wait_group 0;\n" ::);
        }
        __syncthreads();

        const unsigned aBuf = aB + (unsigned)((kt & 1) * BM * LDSR) * 4u;
        const unsigned bBuf = bB + (unsigned)((kt & 1) * BN * LDSR) * 4u;
#pragma unroll
        for (int ks = 0; ks < 4; ks++) {
            const int kk = ks * 8;
            unsigned af[MM][4], bf[MN / 2][4];
#pragma unroll
            for (int im = 0; im < MM; im++) {
                ldsm_x4(af[im], aBuf + (unsigned)(im * 16 * LDSR + kk) * 4u);
                RNA4(af[im]);
            }
#pragma unroll
            for (int p = 0; p < MN / 2; p++) {
                ldsm_x4(bf[p], bBuf + (unsigned)(p * 16 * LDSR + kk) * 4u);
                RNA4(bf[p]);
            }
#pragma unroll
            for (int im = 0; im < MM; im++)
#pragma unroll
                for (int p = 0; p < MN / 2; p++) {
                    mma8(acc[im][2 * p], af[im], bf[p]);
                    mma8(acc[im][2 * p + 1], af[im], bf[p] + 2);
                }
        }
        __syncthreads();
    }

#pragma unroll
    for (int im = 0; im < MM; im++) {
        int row0 = bm + wm * TM + im * 16 + g;
#pragma unroll
        for (int in = 0; in < MN; in++) {
            int col = bn + wn * TN + in * 8 + 2 * tg;
            float2 bb = *(const float2*)(bias + col);
            float* c = acc[im][in];
            *(float2*)(C + (size_t)row0 * N + col) = make_float2(c[0] + bb.x, c[1] + bb.y);
            *(float2*)(C + (size_t)(row0 + 8) * N + col) = make_float2(c[2] + bb.x, c[3] + bb.y);
        }
    }
}

// ---- dual GEMM: blocks 0..199 compute uk, 200..319 compute gi (one launch) --
__global__ void __launch_bounds__(256, 2)
k_gemm_dual(const float* __restrict__ enc, const float* __restrict__ ua_w,
            const float* __restrict__ ua_b, float* __restrict__ uk,
            const float* __restrict__ emb, const float* __restrict__ w_ih,
            const float* __restrict__ b_ih, float* __restrict__ gi,
            const int* __restrict__ target) {
    extern __shared__ float sm[];
    const int bid = blockIdx.x;
    if (bid == 0 && threadIdx.x < 2 * T) g_cnt[threadIdx.x] = 0;

    if (bid < 200) {
        int bx = bid & 7, by = bid >> 3;
        gemm128_body(enc, ua_w, ua_b, uk, H, H2, by * 128, bx * 128,
                     false, nullptr, sm);
    } else {
        int idx = bid - 200;
        int bx = idx % 24, by = idx / 24;
        gemm128_body(emb, w_ih, b_ih, gi, H3, E, by * 128, bx * 128,
                     true, target, sm);
    }
}

// ---- wq GEMM (stand-alone, same proven body) --------------------------------
__global__ void __launch_bounds__(256, 2)
k_gemm_wq(const float* __restrict__ A, const float* __restrict__ W,
          const float* __restrict__ bias, float* __restrict__ C) {
    extern __shared__ float sm[];
    gemm128_body(A, W, bias, C, H, H, blockIdx.y * 128, blockIdx.x * 128,
                 false, nullptr, sm);
}

// ---------------- persistent GRU, weight-resident in smem -------------------
// Grid (16,1,8) = 128 blocks, 1 block/SM (smem) -> co-resident; counter barrier.
__global__ void __launch_bounds__(256)
k_gru_all(const float* __restrict__ hidden, const float* __restrict__ whh,
          const float* __restrict__ gi_all, const float* __restrict__ b_hh_,
          float* __restrict__ part, float* __restrict__ hs) {
    constexpr int BM = 64, BN = 192, WM = 2, WN = 4;
    constexpr int NT = 256;
    constexpr int TM = BM / WM, TN = BN / WN;   // 32, 48
    constexpr int MM = TM / 16, MN = TN / 8;    // 2, 6
    constexpr int KLEN = H / KSPLIT;            // 128
    constexpr int LDSR = KLEN + 4;              // 132 floats = 528 B rows
    constexpr int NBLK = (H3 / BN) * KSPLIT;    // 128
    constexpr int A_CP = BM * (KLEN / 4) / NT;  // 8
    constexpr int B_CP = BN * (KLEN / 4) / NT;  // 24

    extern __shared__ float sm[];
    float* Bs = sm;                 // [BN][LDSR]  weights, resident
    float* As = sm + BN * LDSR;     // [BM][LDSR]  hprev slice, per step

    const int tid = threadIdx.x;
    const int warp = tid >> 5, lane = tid & 31;
    const int wm = warp / WN, wn = warp % WN;
    const int g = lane >> 2, tg = lane & 3;
    const int bn = blockIdx.x * BN;
    const int z = blockIdx.z;
    const int kstart = z * KLEN;
    float* C = part + (size_t)z * B * H3;

    // ---- load W_hh tile once (192 x 128 floats) ----
#pragma unroll
    for (int i = 0; i < B_CP; i++) {
        int idx = tid + i * NT;
        int r = idx >> 5, kq = idx & 31;
        cp16(Bs + r * LDSR + kq * 4, whh + (size_t)(bn + r) * H + kstart + kq * 4);
    }
    asm volatile("cp.async.commit_group;\n" ::);

    const int rw = lane & 7;
    const unsigned aB = (unsigned)__cvta_generic_to_shared(As) +
        ((unsigned)((wm * TM + rw + 8 * ((lane >> 3) & 1)) * LDSR + 4 * (lane >> 4))) * 4u;
    const unsigned bB = (unsigned)__cvta_generic_to_shared(Bs) +
        ((unsigned)((wn * TN + rw + 8 * (lane >> 4)) * LDSR + 4 * ((lane >> 3) & 1))) * 4u;

    const int gtid = (z * gridDim.x + blockIdx.x) * NT + tid;   // 0..32767

    for (int t = 0; t < T; t++) {
        const float* hprev = (t == 0) ? hidden : hs + (size_t)(t - 1) * B * H;
        const float* gi = gi_all + (size_t)t * B * H3;

        // ---- load hprev slice (64 x 128 floats) ----
#pragma unroll
        for (int i = 0; i < A_CP; i++) {
            int idx = tid + i * NT;
            int r = idx >> 5, kq = idx & 31;
            cp16(As + r * LDSR + kq * 4, hprev + (size_t)r * H + kstart + kq * 4);
        }
        asm volatile("cp.async.commit_group;\n" ::);
        asm volatile("cp.async.wait_group 0;\n" ::);
        __syncthreads();

        // ---- MMA: acc = As(64xKLEN) x Bs(192xKLEN)^T ----
        float acc[MM][MN][4];
#pragma unroll
        for (int im = 0; im < MM; im++)
#pragma unroll
            for (int in = 0; in < MN; in++)
#pragma unroll
                for (int q = 0; q < 4; q++) acc[im][in][q] = 0.f;

#pragma unroll
        for (int ks = 0; ks < KLEN / 8; ks++) {
            const int kk = ks * 8;
            unsigned af[MM][4], bf[MN / 2][4];
#pragma unroll
            for (int im = 0; im < MM; im++) {
                ldsm_x4(af[im], aB + (unsigned)(im * 16 * LDSR + kk) * 4u);
                RNA4(af[im]);
            }
#pragma unroll
            for (int p = 0; p < MN / 2; p++) {
                ldsm_x4(bf[p], bB + (unsigned)(p * 16 * LDSR + kk) * 4u);
                RNA4(bf[p]);
            }
#pragma unroll
            for (int im = 0; im < MM; im++)
#pragma unroll
                for (int p = 0; p < MN / 2; p++) {
                    mma8(acc[im][2 * p], af[im], bf[p]);
                    mma8(acc[im][2 * p + 1], af[im], bf[p] + 2);
                }
        }

        // ---- write partials ----
#pragma unroll
        for (int im = 0; im < MM; im++) {
            int row0 = wm * TM + im * 16 + g;
#pragma unroll
            for (int in = 0; in < MN; in++) {
                int col = bn + wn * TN + in * 8 + 2 * tg;
                float* c = acc[im][in];
                *(float2*)(C + (size_t)row0 * H3 + col) = make_float2(c[0], c[1]);
                *(float2*)(C + (size_t)(row0 + 8) * H3 + col) = make_float2(c[2], c[3]);
            }
        }

        // ---- barrier: partials visible ----
        __syncthreads();
        if (tid == 0) {
            __threadfence();
            atomicAdd(&g_cnt[2 * t], 1);
            while (((volatile int*)g_cnt)[2 * t] < NBLK) {}
            __threadfence();
        }
        __syncthreads();

        // ---- gate (vectorized): one float4 group of j per thread ----
        float* hnew = hs + (size_t)t * B * H;
        if (gtid < B * H / 4) {
            int idx4 = gtid * 4;
            int b = idx4 / H, j = idx4 % H;
            float4 hr = *(const float4*)(b_hh_ + j);
            float4 hz = *(const float4*)(b_hh_ + H + j);
            float4 hn = *(const float4*)(b_hh_ + 2 * H + j);
#pragma unroll
            for (int s = 0; s < KSPLIT; s++) {
                const float* p = part + (size_t)s * B * H3 + (size_t)b * H3;
                float4 pr = __ldcg((const float4*)(p + j));
                float4 pz = __ldcg((const float4*)(p + H + j));
                float4 pn = __ldcg((const float4*)(p + 2 * H + j));
                hr.x += pr.x; hr.y += pr.y; hr.z += pr.z; hr.w += pr.w;
                hz.x += pz.x; hz.y += pz.y; hz.z += pz.z; hz.w += pz.w;
                hn.x += pn.x; hn.y += pn.y; hn.z += pn.z; hn.w += pn.w;
            }
            const float* gib = gi + (size_t)b * H3;
            float4 ir = *(const float4*)(gib + j);
            float4 iz = *(const float4*)(gib + H + j);
            float4 in_ = *(const float4*)(gib + 2 * H + j);
            float4 hp = __ldcg((const float4*)(hprev + (size_t)b * H + j));
            float4 o;
            {
                float r = 1.f / (1.f + expf(-(ir.x + hr.x)));
                float z_ = 1.f / (1.f + expf(-(iz.x + hz.x)));
                o.x = (1.f - z_) * tanhf(in_.x + r * hn.x) + z_ * hp.x;
            }
            {
                float r = 1.f / (1.f + expf(-(ir.y + hr.y)));
                float z_ = 1.f / (1.f + expf(-(iz.y + hz.y)));
                o.y = (1.f - z_) * tanhf(in_.y + r * hn.y) + z_ * hp.y;
            }
            {
                float r = 1.f / (1.f + expf(-(ir.z + hr.z)));
                float z_ = 1.f / (1.f + expf(-(iz.z + hz.z)));
                o.z = (1.f - z_) * tanhf(in_.z + r * hn.z) + z_ * hp.z;
            }
            {
                float r = 1.f / (1.f + expf(-(ir.w + hr.w)));
                float z_ = 1.f / (1.f + expf(-(iz.w + hz.w)));
                o.w = (1.f - z_) * tanhf(in_.w + r * hn.w) + z_ * hp.w;
            }
            *(float4*)(hnew + (size_t)b * H + j) = o;
        }

        // ---- barrier: h_t visible before next step's A load ----
        if (t + 1 < T) {
            __syncthreads();
            if (tid == 0) {
                __threadfence();
                atomicAdd(&g_cnt[2 * t + 1], 1);
                while (((volatile int*)g_cnt)[2 * t + 1] < NBLK) {}
                __threadfence();
            }
            __syncthreads();
        }
    }
}

// ---------------- elementwise / attention kernels ----------------

// scores: grid (B, 7, 2); one s per warp (56 slots cover S=50), z selects 5
// decode steps. wq[5][H] + va_w staged in smem. 3 blocks/SM via launch bounds.
__global__ void __launch_bounds__(256, 3)
k_scores(const float* __restrict__ wq, const float* __restrict__ uk,
         const float* __restrict__ va_w, const float* __restrict__ va_b,
         float* __restrict__ scores) {
    constexpr int TB = T / 2;     // 5 steps per block
    __shared__ float wqs[TB][H];  // 20 KB
    __shared__ float vas[H];      // 4 KB
    int b = blockIdx.x, th0 = blockIdx.z * TB;
    int tid = threadIdx.x;
    for (int i = tid; i < TB * H; i += 256) {
        wqs[0][i] = wq[(size_t)((i / H + th0) * B + b) * H + (i % H)];
    }
    for (int i = tid; i < H; i += 256) vas[i] = va_w[i];
    __syncthreads();

    int warp = tid >> 5, lane = tid & 31;
    int s = blockIdx.y * 8 + warp;
    if (s >= S) return;

    const float4* ukr = (const float4*)(uk + (size_t)(s * B + b) * H);
    float acc[TB];
#pragma unroll
    for (int t = 0; t < TB; t++) acc[t] = 0.f;
#pragma unroll
    for (int i = 0; i < H / 128; i++) {
        float4 u = ukr[lane + i * 32];
        float4 v = *(const float4*)&vas[(lane + i * 32) * 4];
#pragma unroll
        for (int t = 0; t < TB; t++) {
            float4 w = *(const float4*)&wqs[t][(lane + i * 32) * 4];
            float a = acc[t];
            a = fmaf(v.x, tanha(w.x + u.x), a);
            a = fmaf(v.y, tanha(w.y + u.y), a);
            a = fmaf(v.z, tanha(w.z + u.z), a);
            a = fmaf(v.w, tanha(w.w + u.w), a);
            acc[t] = a;
        }
    }
    float vb = va_b[0];
#pragma unroll
    for (int t = 0; t < TB; t++) {
#pragma unroll
        for (int o = 16; o; o >>= 1) acc[t] += __shfl_xor_sync(0xffffffffu, acc[t], o);
        if (lane == 0) scores[(size_t)((th0 + t) * B + b) * S + s] = acc[t] + vb;
    }
}

// softmax (in-smem) + context + log_softmax + h_last copy: one block per b.
__global__ void k_context(const float* __restrict__ scores,
                          const float* __restrict__ enc,
                          const float* __restrict__ hs_last,
                          float* __restrict__ out, int do_hlast) {
    int b = blockIdx.x;
    int tid = threadIdx.x;
    int warp = tid >> 5, lane = tid & 31;
    __shared__ float w[T][S];
    __shared__ float red[8];

    for (int i = tid; i < T * S; i += 256) {
        int t = i / S, s = i % S;
        w[t][s] = scores[(size_t)(t * B + b) * S + s];
    }
    __syncthreads();

    for (int t = warp; t < T; t += 8) {
        float v0 = (lane < S) ? w[t][lane] : -1e30f;
        float v1 = (lane + 32 < S) ? w[t][lane + 32] : -1e30f;
        float m = fmaxf(v0, v1);
#pragma unroll
        for (int o = 16; o; o >>= 1) m = fmaxf(m, __shfl_xor_sync(0xffffffffu, m, o));
        float e0 = (lane < S) ? expf(v0 - m) : 0.f;
        float e1 = (lane + 32 < S) ? expf(v1 - m) : 0.f;
        float sum = e0 + e1;
#pragma unroll
        for (int o = 16; o; o >>= 1) sum += __shfl_xor_sync(0xffffffffu, sum, o);
        float inv = 1.f / sum;
        if (lane < S) w[t][lane] = e0 * inv;
        if (lane + 32 < S) w[t][lane + 32] = e1 * inv;
    }
    __syncthreads();

    float c[T][8];
#pragma unroll
    for (int t = 0; t < T; t++)
#pragma unroll
        for (int i = 0; i < 8; i++) c[t][i] = 0.f;

    for (int s = 0; s < S; s++) {
        const float* kr = enc + (size_t)(s * B + b) * H2;
        float4 k0 = *(const float4*)(kr + tid * 8);
        float4 k1 = *(const float4*)(kr + tid * 8 + 4);
        float kv[8] = {k0.x, k0.y, k0.z, k0.w, k1.x, k1.y, k1.z, k1.w};
#pragma unroll
        for (int t = 0; t < T; t++) {
            float ws = w[t][s];
#pragma unroll
            for (int i = 0; i < 8; i++) c[t][i] = fmaf(ws, kv[i], c[t][i]);
        }
    }

    for (int t = 0; t < T; t++) {
        float m = c[t][0];
#pragma unroll
        for (int i = 1; i < 8; i++) m = fmaxf(m, c[t][i]);
#pragma unroll
        for (int o = 16; o; o >>= 1) m = fmaxf(m, __shfl_xor_sync(0xffffffffu, m, o));
        if (lane == 0) red[warp] = m;
        __syncthreads();
        if (tid == 0) {
            float mm = red[0];
            for (int i = 1; i < 8; i++) mm = fmaxf(mm, red[i]);
            red[0] = mm;
        }
        __syncthreads();
        m = red[0];
        __syncthreads();

        float sum = 0.f;
#pragma unroll
        for (int i = 0; i < 8; i++) sum += expf(c[t][i] - m);
#pragma unroll
        for (int o = 16; o; o >>= 1) sum += __shfl_xor_sync(0xffffffffu, sum, o);
        if (lane == 0) red[warp] = sum;
        __syncthreads();
        if (tid == 0) {
            float ss = 0.f;
            for (int i = 1; i < 8; i++) ss += red[i];
            red[0] += ss;
        }
        __syncthreads();
        float lse = m + logf(red[0]);
        __syncthreads();

        float* o_ = out + (size_t)(b * T + t) * H2 + tid * 8;
        *(float4*)o_ = make_float4(c[t][0] - lse, c[t][1] - lse, c[t][2] - lse, c[t][3] - lse);
        *(float4*)(o_ + 4) = make_float4(c[t][4] - lse, c[t][5] - lse, c[t][6] - lse, c[t][7] - lse);
    }

    if (do_hlast) {
        float* dst = out + (size_t)B * T * H2 + (size_t)b * H;
        const float* src = hs_last + (size_t)b * H;
#pragma unroll
        for (int i = 0; i < H / 256; i++) dst[tid + i * 256] = src[tid + i * 256];
    }
}

// ---------------- launch (single default stream, deterministic) -------------
extern "C" void kernel_launch(void* const* d_in, const int* in_sizes, int n_in,
                              void* d_out, int out_size) {
    const float* enc    = (const float*)d_in[0];
    const float* hidden = (const float*)d_in[1];
    const int*   target = (const int*)d_in[2];
    const float* emb    = (const float*)d_in[3];
    const float* w_ih   = (const float*)d_in[4];
    const float* w_hh   = (const float*)d_in[5];
    const float* b_ih   = (const float*)d_in[6];
    const float* b_hh   = (const float*)d_in[7];
    const float* wa_w   = (const float*)d_in[8];
    const float* wa_b   = (const float*)d_in[9];
    const float* ua_w   = (const float*)d_in[10];
    const float* ua_b   = (const float*)d_in[11];
    const float* va_w   = (const float*)d_in[12];
    const float* va_b   = (const float*)d_in[13];
    float* out = (float*)d_out;

    float *gi, *ghp, *hs, *uk, *wq, *sc;
    cudaGetSymbolAddress((void**)&gi, g_gi);
    cudaGetSymbolAddress((void**)&ghp, g_ghp);
    cudaGetSymbolAddress((void**)&hs, g_hs);
    cudaGetSymbolAddress((void**)&uk, g_uk);
    cudaGetSymbolAddress((void**)&wq, g_wq);
    cudaGetSymbolAddress((void**)&sc, g_sc);

    constexpr int LDSR = 36;
    const int smem_big = 2 * (128 + 128) * LDSR * 4;        // 73728 B
    const int smem_gru = (192 + 64) * (128 + 4) * 4;        // 135168 B
    cudaFuncSetAttribute((const void*)k_gemm_dual,
                         cudaFuncAttributeMaxDynamicSharedMemorySize, smem_big);
    cudaFuncSetAttribute((const void*)k_gemm_wq,
                         cudaFuncAttributeMaxDynamicSharedMemorySize, smem_big);
    cudaFuncSetAttribute((const void*)k_gru_all,
                         cudaFuncAttributeMaxDynamicSharedMemorySize, smem_gru);

    // uk (200 tiles) + gi (120 tiles) in one full-machine launch; also resets
    // the GRU barrier counters (block 0) before k_gru_all runs.
    k_gemm_dual<<<320, 256, smem_big>>>(enc, ua_w, ua_b, uk,
                                        emb, w_ih, b_ih, gi, target);

    // persistent GRU: all T steps, W_hh resident in smem (128 co-resident blocks)
    k_gru_all<<<dim3(H3 / 192, 1, KSPLIT), 256, smem_gru>>>(
        hidden, w_hh, gi, b_hh, ghp, hs);

    // wq = hs @ wa_w^T + wa_b   [640, 1024], K=1024
    k_gemm_wq<<<dim3(H / 128, (T * B) / 128), 256, smem_big>>>(hs, wa_w, wa_b, wq);

    // attention scores: one s per warp, T split in halves
    k_scores<<<dim3(B, 7, 2), 256>>>(wq, uk, va_w, va_b, sc);

    int do_hlast = (out_size >= B * T * H2 + B * H) ? 1 : 0;
    k_context<<<B, 256>>>(sc, enc, hs + (size_t)(T - 1) * B * H, out, do_hlast);
}